// round 1
// baseline (speedup 1.0000x reference)
#include <cuda_runtime.h>
#include <math.h>

#define COND 128
#define NPIX (8 * 256 * 256)
#define TPB  128

// ---------------- device scratch (no allocations allowed) ----------------
__device__ float g_z1[8][64];
__device__ float g_z2[8][64];
__device__ float g_z3[8][64];
__device__ float g_z4[8][4];
__device__ __align__(16) float g_w1s[64][32];
__device__ __align__(16) float g_w2s[64][64];
__device__ __align__(16) float g_w3s[64][64];
__device__ __align__(16) float g_w4s[4][64];
__device__ float g_fw[8];

// scales: 1/sqrt(160), 1/sqrt(192)
#define S1 0.07905694150420948f
#define S2 0.07216878364870323f
#define SQRT2F 1.41421356237309515f

// ---------------- prep: per-batch cond bias + scaled weights ----------------
__global__ void prep_kernel(const float* __restrict__ c, const float* __restrict__ fu,
                            const float* __restrict__ w1, const float* __restrict__ b1,
                            const float* __restrict__ w2, const float* __restrict__ b2,
                            const float* __restrict__ w3, const float* __restrict__ b3,
                            const float* __restrict__ w4, const float* __restrict__ b4)
{
    int t = blockIdx.x * blockDim.x + threadIdx.x;
    int stride = gridDim.x * blockDim.x;

    if (t < 8) {
        float lim = (float)(t + 1) / 9.0f;
        float w = (fu[0] - lim) * 9.0f;
        g_fw[t] = fminf(fmaxf(w, 0.0f), 1.0f);
    }
    // scaled pixel-part weights
    for (int idx = t; idx < 64 * 32; idx += stride) {
        int j = idx >> 5, k = idx & 31;
        g_w1s[j][k] = w1[j * 160 + k] * S1;
    }
    for (int idx = t; idx < 64 * 64; idx += stride) {
        int j = idx >> 6, k = idx & 63;
        g_w2s[j][k] = w2[j * 192 + k] * S2;
        g_w3s[j][k] = w3[j * 192 + k] * S2;
    }
    for (int idx = t; idx < 4 * 64; idx += stride) {
        int j = idx >> 6, k = idx & 63;
        g_w4s[j][k] = w4[j * 192 + k] * S2;
    }
    // per-batch cond biases
    for (int idx = t; idx < 8 * 64; idx += stride) {
        int b = idx >> 6, j = idx & 63;
        const float* cb = c + b * COND;
        float a1 = 0.f, a2 = 0.f, a3 = 0.f;
        for (int k = 0; k < COND; k++) {
            float cv = cb[k];
            a1 = fmaf(cv, w1[j * 160 + 32 + k], a1);
            a2 = fmaf(cv, w2[j * 192 + 64 + k], a2);
            a3 = fmaf(cv, w3[j * 192 + 64 + k], a3);
        }
        g_z1[b][j] = b1[j] + S1 * a1;
        g_z2[b][j] = b2[j] + S2 * a2;
        g_z3[b][j] = b3[j] + S2 * a3;
    }
    for (int idx = t; idx < 8 * 4; idx += stride) {
        int b = idx >> 2, j = idx & 3;
        const float* cb = c + b * COND;
        float a4 = 0.f;
        for (int k = 0; k < COND; k++) a4 = fmaf(cb[k], w4[j * 192 + 64 + k], a4);
        g_z4[b][j] = b4[j] + S2 * a4;
    }
}

// ---------------- fully-unrolled 64->64 layer (register resident) ----------------
__device__ __forceinline__ void layer64(float* __restrict__ ho, const float* __restrict__ hi,
                                        const float (*__restrict__ sw)[64],
                                        const float* __restrict__ sz)
{
#pragma unroll
    for (int j = 0; j < 64; j++) {
        float acc = sz[j];
        const float4* wr = (const float4*)sw[j];
#pragma unroll
        for (int k = 0; k < 16; k++) {
            float4 w = wr[k];
            acc = fmaf(hi[4 * k + 0], w.x, acc);
            acc = fmaf(hi[4 * k + 1], w.y, acc);
            acc = fmaf(hi[4 * k + 2], w.z, acc);
            acc = fmaf(hi[4 * k + 3], w.w, acc);
        }
        ho[j] = fmaxf(acc, 0.2f * acc) * SQRT2F;
    }
}

// ---------------- main kernel: one pixel per thread ----------------
__global__ __launch_bounds__(TPB) void decoder_kernel(const float* __restrict__ coords,
                                                      float* __restrict__ out)
{
    __shared__ __align__(16) float s_w1[64][32];
    __shared__ __align__(16) float s_w2[64][64];
    __shared__ __align__(16) float s_w3[64][64];
    __shared__ __align__(16) float s_w4[4][64];
    __shared__ float s_z1[64], s_z2[64], s_z3[64], s_z4[4];
    __shared__ float s_fw[8];

    const int tid = threadIdx.x;
    const int pixel = blockIdx.x * TPB + tid;
    const int batch = pixel >> 16;  // 65536 pixels per batch; blocks never straddle

    // cooperative stage of weights into shared
    for (int i = tid; i < 512; i += TPB)  ((float4*)s_w1)[i] = ((const float4*)g_w1s)[i];
    for (int i = tid; i < 1024; i += TPB) ((float4*)s_w2)[i] = ((const float4*)g_w2s)[i];
    for (int i = tid; i < 1024; i += TPB) ((float4*)s_w3)[i] = ((const float4*)g_w3s)[i];
    for (int i = tid; i < 64; i += TPB)   ((float4*)s_w4)[i] = ((const float4*)g_w4s)[i];
    for (int i = tid; i < 64; i += TPB) {
        s_z1[i] = g_z1[batch][i];
        s_z2[i] = g_z2[batch][i];
        s_z3[i] = g_z3[batch][i];
    }
    if (tid < 4) s_z4[tid] = g_z4[batch][tid];
    if (tid < 8) s_fw[tid] = g_fw[tid];
    __syncthreads();

    const float2 xy = ((const float2*)coords)[pixel];

    // sinusoidal embedding via double-angle recurrence (2 accurate sincos total)
    float sx, cx, sy, cy;
    sincosf(xy.x * 0.1f, &sx, &cx);
    sincosf(xy.y * 0.1f, &sy, &cy);

    float e[32];
#pragma unroll
    for (int i = 0; i < 8; i++) {
        float w = s_fw[i];
        e[4 * i + 0] = sx * w;
        e[4 * i + 1] = sy * w;
        e[4 * i + 2] = cx * w;
        e[4 * i + 3] = cy * w;
        if (i < 7) {
            float nsx = 2.0f * sx * cx;
            float ncx = fmaf(-2.0f * sx, sx, 1.0f);
            float nsy = 2.0f * sy * cy;
            float ncy = fmaf(-2.0f * sy, sy, 1.0f);
            sx = nsx; cx = ncx; sy = nsy; cy = ncy;
        }
    }

    // layer 1: 32 -> 64
    float hA[64];
#pragma unroll
    for (int j = 0; j < 64; j++) {
        float acc = s_z1[j];
        const float4* wr = (const float4*)s_w1[j];
#pragma unroll
        for (int k = 0; k < 8; k++) {
            float4 w = wr[k];
            acc = fmaf(e[4 * k + 0], w.x, acc);
            acc = fmaf(e[4 * k + 1], w.y, acc);
            acc = fmaf(e[4 * k + 2], w.z, acc);
            acc = fmaf(e[4 * k + 3], w.w, acc);
        }
        hA[j] = fmaxf(acc, 0.2f * acc) * SQRT2F;
    }

    // layers 2 & 3: 64 -> 64
    float hB[64];
    layer64(hB, hA, s_w2, s_z2);
    layer64(hA, hB, s_w3, s_z3);

    // layer 4: 64 -> 4 (no activation)
    float o[4];
#pragma unroll
    for (int jj = 0; jj < 4; jj++) {
        float acc = s_z4[jj];
        const float4* wr = (const float4*)s_w4[jj];
#pragma unroll
        for (int k = 0; k < 16; k++) {
            float4 w = wr[k];
            acc = fmaf(hA[4 * k + 0], w.x, acc);
            acc = fmaf(hA[4 * k + 1], w.y, acc);
            acc = fmaf(hA[4 * k + 2], w.z, acc);
            acc = fmaf(hA[4 * k + 3], w.w, acc);
        }
        o[jj] = acc;
    }

    // radius mask
    float r = sqrtf(fmaf(xy.x, xy.x, xy.y * xy.y));
    float m = 1.0f - tanhf(fmaxf(r - 1.0f, 0.0f));

    float4 ov;
    ov.x = o[0] * m;
    ov.y = o[1] * m;
    ov.z = o[2] * m;
    ov.w = o[3] * m;
    ((float4*)out)[pixel] = ov;
}

// ---------------- launch ----------------
extern "C" void kernel_launch(void* const* d_in, const int* in_sizes, int n_in,
                              void* d_out, int out_size)
{
    const float* coords = (const float*)d_in[0];
    const float* c      = (const float*)d_in[1];
    const float* fu     = (const float*)d_in[2];
    const float* w1     = (const float*)d_in[3];
    const float* b1     = (const float*)d_in[4];
    const float* w2     = (const float*)d_in[5];
    const float* b2     = (const float*)d_in[6];
    const float* w3     = (const float*)d_in[7];
    const float* b3     = (const float*)d_in[8];
    const float* w4     = (const float*)d_in[9];
    const float* b4     = (const float*)d_in[10];
    float* out = (float*)d_out;

    prep_kernel<<<64, 256>>>(c, fu, w1, b1, w2, b2, w3, b3, w4, b4);
    decoder_kernel<<<NPIX / TPB, TPB>>>(coords, out);
}

// round 3
// speedup vs baseline: 4.0495x; 4.0495x over previous
#include <cuda_runtime.h>
#include <cuda_bf16.h>
#include <cstdint>
#include <math.h>

#define S1 0.07905694150420948f   // 1/sqrt(160)
#define S2 0.07216878364870323f   // 1/sqrt(192)
#define SQRT2F 1.41421356237309515f
#define NCHUNKS 16384             // 524288 px / 32 per warp-chunk
#define GRID_MAIN 304
#define TPB 128
#define NWARPS_TOTAL (GRID_MAIN * (TPB / 32))

// ---- weight fragment layout (u32 indices inside g_wfrag / smem) ----
// per frag-slot: ((ntile*KT + kt)*32 + lane)*2 + reg
#define F1H_OFF 0        // [8 ntile][2 kt][32 lane][2 reg] = 1024 u32
#define F1L_OFF 1024
#define F2H_OFF 2048     // [8][4][32][2] = 2048 u32
#define F2L_OFF 4096
#define F3H_OFF 6144
#define F3L_OFF 8192
#define F4H_OFF 10240    // [1][4][32][2] = 256 u32
#define F4L_OFF 10496
#define WFRAG_U32 10752

// ---- shared memory byte offsets ----
#define SW_BASE   0               // weight frags: 43008 B
#define SM_ZBASE  43008           // 1608 floats: z1[512] z2[512] z3[512] z4[64] fw[8]
#define SM_EH     49440           // 128 rows x 17 u32
#define SM_EL     58144
#define SM_MASK   66848           // 128 floats
#define SM_TOTAL  67360

// ---- device globals (prep outputs) ----
__device__ __align__(16) uint32_t g_wfrag[WFRAG_U32];
__device__ __align__(16) float    g_zall[1608];

// ---------------- helpers ----------------
__device__ __forceinline__ void mma16816(float* c, const uint32_t* a, const uint32_t* b) {
    asm volatile(
        "mma.sync.aligned.m16n8k16.row.col.f32.bf16.bf16.f32 "
        "{%0,%1,%2,%3}, {%4,%5,%6,%7}, {%8,%9}, {%0,%1,%2,%3};"
        : "+f"(c[0]), "+f"(c[1]), "+f"(c[2]), "+f"(c[3])
        : "r"(a[0]), "r"(a[1]), "r"(a[2]), "r"(a[3]), "r"(b[0]), "r"(b[1]));
}

__device__ __forceinline__ void split2(float v0, float v1, uint32_t& hi, uint32_t& lo) {
    __nv_bfloat16 h0 = __float2bfloat16(v0);
    __nv_bfloat16 h1 = __float2bfloat16(v1);
    float l0 = v0 - __bfloat162float(h0);
    float l1 = v1 - __bfloat162float(h1);
    __nv_bfloat16 g0 = __float2bfloat16(l0);
    __nv_bfloat16 g1 = __float2bfloat16(l1);
    uint16_t u0 = *(uint16_t*)&h0, u1 = *(uint16_t*)&h1;
    uint16_t w0 = *(uint16_t*)&g0, w1 = *(uint16_t*)&g1;
    hi = ((uint32_t)u1 << 16) | u0;   // low half = even-k element
    lo = ((uint32_t)w1 << 16) | w0;
}

__device__ __forceinline__ float actf(float t) { return fmaxf(t, 0.2f * t) * SQRT2F; }

// ---------------- prep kernel ----------------
__global__ void prep_kernel(const float* __restrict__ c, const float* __restrict__ fu,
                            const float* __restrict__ w1, const float* __restrict__ b1,
                            const float* __restrict__ w2, const float* __restrict__ b2,
                            const float* __restrict__ w3, const float* __restrict__ b3,
                            const float* __restrict__ w4, const float* __restrict__ b4)
{
    int t = blockIdx.x * blockDim.x + threadIdx.x;
    int stride = gridDim.x * blockDim.x;

    // freq weights
    if (t < 8) {
        float lim = (float)(t + 1) / 9.0f;
        float w = (fu[0] - lim) * 9.0f;
        g_zall[1600 + t] = fminf(fmaxf(w, 0.0f), 1.0f);
    }

    // weight fragments (5376 hi/lo slot pairs)
    for (int s = t; s < 5376; s += stride) {
        int layer, rel, Hoff, Loff, KT;
        if (s < 1024)      { layer = 1; rel = s;        Hoff = F1H_OFF; Loff = F1L_OFF; KT = 2; }
        else if (s < 3072) { layer = 2; rel = s - 1024; Hoff = F2H_OFF; Loff = F2L_OFF; KT = 4; }
        else if (s < 5120) { layer = 3; rel = s - 3072; Hoff = F3H_OFF; Loff = F3L_OFF; KT = 4; }
        else               { layer = 4; rel = s - 5120; Hoff = F4H_OFF; Loff = F4L_OFF; KT = 4; }
        int reg  = rel & 1;
        int lane = (rel >> 1) & 31;
        int tk   = (rel >> 6) % KT;
        int nt   = (rel >> 6) / KT;
        int gg = lane >> 2, cc = lane & 3;
        int n = nt * 8 + gg;
        int k0 = tk * 16 + 2 * cc + (reg ? 8 : 0);
        float v0, v1;
        if (layer == 1)      { v0 = w1[n * 160 + k0] * S1; v1 = w1[n * 160 + k0 + 1] * S1; }
        else if (layer == 2) { v0 = w2[n * 192 + k0] * S2; v1 = w2[n * 192 + k0 + 1] * S2; }
        else if (layer == 3) { v0 = w3[n * 192 + k0] * S2; v1 = w3[n * 192 + k0 + 1] * S2; }
        else { v0 = (n < 4) ? w4[n * 192 + k0] * S2 : 0.0f;
               v1 = (n < 4) ? w4[n * 192 + k0 + 1] * S2 : 0.0f; }
        uint32_t hw, lw;
        split2(v0, v1, hw, lw);
        g_wfrag[Hoff + rel] = hw;
        g_wfrag[Loff + rel] = lw;
    }

    // per-batch cond biases: z1,z2,z3 (8x64) and z4 (8x8, cols>=4 zero)
    for (int idx = t; idx < 8 * 64; idx += stride) {
        int b = idx >> 6, j = idx & 63;
        const float* cb = c + b * 128;
        float a1 = 0.f, a2 = 0.f, a3 = 0.f;
        for (int k = 0; k < 128; k++) {
            float cv = cb[k];
            a1 = fmaf(cv, w1[j * 160 + 32 + k], a1);
            a2 = fmaf(cv, w2[j * 192 + 64 + k], a2);
            a3 = fmaf(cv, w3[j * 192 + 64 + k], a3);
        }
        g_zall[idx]        = b1[j] + S1 * a1;
        g_zall[512 + idx]  = b2[j] + S2 * a2;
        g_zall[1024 + idx] = b3[j] + S2 * a3;
    }
    for (int idx = t; idx < 8 * 8; idx += stride) {
        int b = idx >> 3, j = idx & 7;
        float v = 0.0f;
        if (j < 4) {
            const float* cb = c + b * 128;
            float a4 = 0.f;
            for (int k = 0; k < 128; k++) a4 = fmaf(cb[k], w4[j * 192 + 64 + k], a4);
            v = b4[j] + S2 * a4;
        }
        g_zall[1536 + idx] = v;
    }
}

// ---------------- per-layer mma (weights from smem fragment arrays) ----------------
template<int KT>
__device__ __forceinline__ void layer_mma(float C[2][8][4],
                                          const uint32_t Ah[2][4][4],
                                          const uint32_t Al[2][4][4],
                                          const char* wh, const char* wl, int lane)
{
#pragma unroll
    for (int n = 0; n < 8; n++) {
        uint2 bh[KT], bl[KT];
#pragma unroll
        for (int kt = 0; kt < KT; kt++) {
            int off = ((n * KT + kt) * 32 + lane) * 8;
            bh[kt] = *(const uint2*)(wh + off);
            bl[kt] = *(const uint2*)(wl + off);
        }
#pragma unroll
        for (int m = 0; m < 2; m++)
#pragma unroll
            for (int kt = 0; kt < KT; kt++) {
                mma16816(C[m][n], Ah[m][kt], (const uint32_t*)&bh[kt]);
                mma16816(C[m][n], Ah[m][kt], (const uint32_t*)&bl[kt]);
                mma16816(C[m][n], Al[m][kt], (const uint32_t*)&bh[kt]);
            }
    }
}

// C (post-layer) -> next-layer A fragments, with bias + lrelu + hi/lo split
__device__ __forceinline__ void epilogue(const float C[2][8][4], const float* z, int c,
                                         uint32_t Ah[2][4][4], uint32_t Al[2][4][4])
{
#pragma unroll
    for (int kt = 0; kt < 4; kt++) {
        const int n0 = 2 * kt, n1 = 2 * kt + 1;
        float2 z0 = *(const float2*)(z + n0 * 8 + 2 * c);
        float2 z1 = *(const float2*)(z + n1 * 8 + 2 * c);
#pragma unroll
        for (int m = 0; m < 2; m++) {
            split2(actf(C[m][n0][0] + z0.x), actf(C[m][n0][1] + z0.y), Ah[m][kt][0], Al[m][kt][0]);
            split2(actf(C[m][n0][2] + z0.x), actf(C[m][n0][3] + z0.y), Ah[m][kt][1], Al[m][kt][1]);
            split2(actf(C[m][n1][0] + z1.x), actf(C[m][n1][1] + z1.y), Ah[m][kt][2], Al[m][kt][2]);
            split2(actf(C[m][n1][2] + z1.x), actf(C[m][n1][3] + z1.y), Ah[m][kt][3], Al[m][kt][3]);
        }
    }
}

// ---------------- main kernel ----------------
__global__ __launch_bounds__(TPB, 3) void decoder_kernel(const float* __restrict__ coords,
                                                         float* __restrict__ out)
{
    extern __shared__ __align__(16) char sm[];
    const int tid = threadIdx.x;
    const int wid = tid >> 5;
    const int lane = tid & 31;
    const int g = lane >> 2, c = lane & 3;

    // ---- stage weights + z/fw into shared (once per CTA) ----
    {
        const uint4* src = (const uint4*)g_wfrag;
        uint4* dst = (uint4*)(sm + SW_BASE);
        for (int i = tid; i < WFRAG_U32 / 4; i += TPB) dst[i] = src[i];
        const float4* zs = (const float4*)g_zall;
        float4* zd = (float4*)(sm + SM_ZBASE);
        for (int i = tid; i < 1608 / 4; i += TPB) zd[i] = zs[i];
    }
    __syncthreads();

    const float* s_fw = (const float*)(sm + SM_ZBASE) + 1600;
    uint32_t* s_eh = (uint32_t*)(sm + SM_EH);
    uint32_t* s_el = (uint32_t*)(sm + SM_EL);
    float* s_mask = (float*)(sm + SM_MASK);

    for (int chunk = blockIdx.x * 4 + wid; chunk < NCHUNKS; chunk += NWARPS_TOTAL) {
        const int pixbase = chunk * 32;
        const int batch = pixbase >> 16;

        // ---- embedding: each lane computes its pixel, writes hi/lo bf16 rows ----
        {
            const int p = pixbase + lane;
            const float2 xy = ((const float2*)coords)[p];
            float sx, cx, sy, cy;
            sincosf(xy.x * 0.1f, &sx, &cx);
            sincosf(xy.y * 0.1f, &sy, &cy);
            float r = sqrtf(fmaf(xy.x, xy.x, xy.y * xy.y));
            s_mask[wid * 32 + lane] = 1.0f - tanhf(fmaxf(r - 1.0f, 0.0f));

            float e[32];
#pragma unroll
            for (int i = 0; i < 8; i++) {
                float w = s_fw[i];
                e[4 * i + 0] = sx * w;
                e[4 * i + 1] = sy * w;
                e[4 * i + 2] = cx * w;
                e[4 * i + 3] = cy * w;
                if (i < 7) {
                    float nsx = 2.0f * sx * cx;
                    float ncx = fmaf(-2.0f * sx, sx, 1.0f);
                    float nsy = 2.0f * sy * cy;
                    float ncy = fmaf(-2.0f * sy, sy, 1.0f);
                    sx = nsx; cx = ncx; sy = nsy; cy = ncy;
                }
            }
            uint32_t* ehr = s_eh + (wid * 32 + lane) * 17;
            uint32_t* elr = s_el + (wid * 32 + lane) * 17;
#pragma unroll
            for (int q = 0; q < 16; q++) {
                uint32_t hw, lw;
                split2(e[2 * q], e[2 * q + 1], hw, lw);
                ehr[q] = hw;
                elr[q] = lw;
            }
        }
        __syncwarp();

        // ---- load layer-1 A fragments from smem ----
        uint32_t Ah[2][4][4], Al[2][4][4];
#pragma unroll
        for (int m = 0; m < 2; m++) {
            const int r0 = wid * 32 + m * 16 + g;
            const uint32_t* eh0 = s_eh + r0 * 17;
            const uint32_t* eh1 = eh0 + 8 * 17;
            const uint32_t* el0 = s_el + r0 * 17;
            const uint32_t* el1 = el0 + 8 * 17;
#pragma unroll
            for (int kt = 0; kt < 2; kt++) {
                Ah[m][kt][0] = eh0[kt * 8 + c];
                Ah[m][kt][1] = eh1[kt * 8 + c];
                Ah[m][kt][2] = eh0[kt * 8 + c + 4];
                Ah[m][kt][3] = eh1[kt * 8 + c + 4];
                Al[m][kt][0] = el0[kt * 8 + c];
                Al[m][kt][1] = el1[kt * 8 + c];
                Al[m][kt][2] = el0[kt * 8 + c + 4];
                Al[m][kt][3] = el1[kt * 8 + c + 4];
            }
        }
        __syncwarp();

        float C[2][8][4];

        // ---- layer 1 (KT=2) ----
#pragma unroll
        for (int m = 0; m < 2; m++)
#pragma unroll
            for (int n = 0; n < 8; n++)
#pragma unroll
                for (int q = 0; q < 4; q++) C[m][n][q] = 0.0f;
        layer_mma<2>(C, Ah, Al, sm + F1H_OFF * 4, sm + F1L_OFF * 4, lane);
        epilogue(C, (const float*)(sm + SM_ZBASE) + batch * 64, c, Ah, Al);

        // ---- layer 2 (KT=4) ----
#pragma unroll
        for (int m = 0; m < 2; m++)
#pragma unroll
            for (int n = 0; n < 8; n++)
#pragma unroll
                for (int q = 0; q < 4; q++) C[m][n][q] = 0.0f;
        layer_mma<4>(C, Ah, Al, sm + F2H_OFF * 4, sm + F2L_OFF * 4, lane);
        epilogue(C, (const float*)(sm + SM_ZBASE) + 512 + batch * 64, c, Ah, Al);

        // ---- layer 3 (KT=4) ----
#pragma unroll
        for (int m = 0; m < 2; m++)
#pragma unroll
            for (int n = 0; n < 8; n++)
#pragma unroll
                for (int q = 0; q < 4; q++) C[m][n][q] = 0.0f;
        layer_mma<4>(C, Ah, Al, sm + F3H_OFF * 4, sm + F3L_OFF * 4, lane);
        epilogue(C, (const float*)(sm + SM_ZBASE) + 1024 + batch * 64, c, Ah, Al);

        // ---- layer 4: single n8 tile (cols 0..3 real) ----
        float C4[2][4];
#pragma unroll
        for (int m = 0; m < 2; m++)
#pragma unroll
            for (int q = 0; q < 4; q++) C4[m][q] = 0.0f;
#pragma unroll
        for (int kt = 0; kt < 4; kt++) {
            const int off = (kt * 32 + lane) * 8;
            uint2 bh = *(const uint2*)(sm + F4H_OFF * 4 + off);
            uint2 bl = *(const uint2*)(sm + F4L_OFF * 4 + off);
#pragma unroll
            for (int m = 0; m < 2; m++) {
                mma16816(C4[m], Ah[m][kt], (const uint32_t*)&bh);
                mma16816(C4[m], Ah[m][kt], (const uint32_t*)&bl);
                mma16816(C4[m], Al[m][kt], (const uint32_t*)&bh);
            }
        }

        // ---- output: threads c<2 hold real cols (2c, 2c+1) ----
        if (c < 2) {
            const float* z4 = (const float*)(sm + SM_ZBASE) + 1536 + batch * 8;
            const float z40 = z4[2 * c], z41 = z4[2 * c + 1];
#pragma unroll
            for (int m = 0; m < 2; m++) {
                const int rloc = wid * 32 + m * 16 + g;
                const int pix0 = pixbase + m * 16 + g;
                const float mk0 = s_mask[rloc];
                const float mk1 = s_mask[rloc + 8];
                float2 o0, o1;
                o0.x = (C4[m][0] + z40) * mk0;
                o0.y = (C4[m][1] + z41) * mk0;
                o1.x = (C4[m][2] + z40) * mk1;
                o1.y = (C4[m][3] + z41) * mk1;
                *(float2*)(out + pix0 * 4 + 2 * c) = o0;
                *(float2*)(out + (pix0 + 8) * 4 + 2 * c) = o1;
            }
        }
    }
}

// ---------------- launch ----------------
extern "C" void kernel_launch(void* const* d_in, const int* in_sizes, int n_in,
                              void* d_out, int out_size)
{
    const float* coords = (const float*)d_in[0];
    const float* c      = (const float*)d_in[1];
    const float* fu     = (const float*)d_in[2];
    const float* w1     = (const float*)d_in[3];
    const float* b1     = (const float*)d_in[4];
    const float* w2     = (const float*)d_in[5];
    const float* b2     = (const float*)d_in[6];
    const float* w3     = (const float*)d_in[7];
    const float* b3     = (const float*)d_in[8];
    const float* w4     = (const float*)d_in[9];
    const float* b4     = (const float*)d_in[10];
    float* out = (float*)d_out;

    cudaFuncSetAttribute(decoder_kernel, cudaFuncAttributeMaxDynamicSharedMemorySize, SM_TOTAL);
    prep_kernel<<<64, 256>>>(c, fu, w1, b1, w2, b2, w3, b3, w4, b4);
    decoder_kernel<<<GRID_MAIN, TPB, SM_TOTAL>>>(coords, out);
}

// round 4
// speedup vs baseline: 6.5830x; 1.6256x over previous
#include <cuda_runtime.h>
#include <cuda_bf16.h>
#include <cstdint>
#include <math.h>

#define S1 0.07905694150420948f   // 1/sqrt(160)
#define S2 0.07216878364870323f   // 1/sqrt(192)
#define SQRT2F 1.41421356237309515f
#define NCHUNKS 16384             // 524288 px / 32 per warp-chunk
#define GRID_MAIN 456             // 3 CTAs/SM x 152 SMs
#define TPB 128
#define NWARPS_TOTAL (GRID_MAIN * (TPB / 32))

// ---- weight fragment layout (u32 indices inside g_wfrag / smem) ----
// per frag-slot: ((ntile*KT + kt)*32 + lane)*2 + reg
#define F1H_OFF 0        // [8 ntile][2 kt][32 lane][2 reg] = 1024 u32
#define F1L_OFF 1024
#define F2H_OFF 2048     // [8][4][32][2] = 2048 u32
#define F2L_OFF 4096
#define F3H_OFF 6144
#define F3L_OFF 8192
#define F4H_OFF 10240    // [1][4][32][2] = 256 u32
#define F4L_OFF 10496
#define WFRAG_U32 10752

// ---- shared memory byte offsets ----
#define SW_BASE   0               // weight frags: 43008 B
#define SM_ZBASE  43008           // 1608 floats: z1[512] z2[512] z3[512] z4[64] fw[8]
#define SM_EH     49440           // 128 rows x 17 u32
#define SM_EL     58144
#define SM_MASK   66848           // 128 floats
#define SM_TOTAL  67360

// ---- device globals (prep outputs) ----
__device__ __align__(16) uint32_t g_wfrag[WFRAG_U32];
__device__ __align__(16) float    g_zall[1608];

// ---------------- helpers ----------------
__device__ __forceinline__ void mma16816(float* c, const uint32_t* a, const uint32_t* b) {
    asm volatile(
        "mma.sync.aligned.m16n8k16.row.col.f32.bf16.bf16.f32 "
        "{%0,%1,%2,%3}, {%4,%5,%6,%7}, {%8,%9}, {%0,%1,%2,%3};"
        : "+f"(c[0]), "+f"(c[1]), "+f"(c[2]), "+f"(c[3])
        : "r"(a[0]), "r"(a[1]), "r"(a[2]), "r"(a[3]), "r"(b[0]), "r"(b[1]));
}

// packed hi/lo split: hi word = {bf16(v1), bf16(v0)}, lo word = residuals
__device__ __forceinline__ void split2(float v0, float v1, uint32_t& hi, uint32_t& lo) {
    uint32_t h;
    asm("cvt.rn.bf16x2.f32 %0, %1, %2;" : "=r"(h) : "f"(v1), "f"(v0));
    float h0 = __uint_as_float(h << 16);
    float h1 = __uint_as_float(h & 0xffff0000u);
    float l0 = v0 - h0;
    float l1 = v1 - h1;
    uint32_t l;
    asm("cvt.rn.bf16x2.f32 %0, %1, %2;" : "=r"(l) : "f"(l1), "f"(l0));
    hi = h; lo = l;
}

__device__ __forceinline__ float actf(float t) { return fmaxf(t, 0.2f * t) * SQRT2F; }

// ---------------- prep kernel ----------------
__global__ void prep_kernel(const float* __restrict__ c, const float* __restrict__ fu,
                            const float* __restrict__ w1, const float* __restrict__ b1,
                            const float* __restrict__ w2, const float* __restrict__ b2,
                            const float* __restrict__ w3, const float* __restrict__ b3,
                            const float* __restrict__ w4, const float* __restrict__ b4)
{
    const int t = blockIdx.x * blockDim.x + threadIdx.x;
    const int stride = gridDim.x * blockDim.x;
    const int warp = t >> 5;
    const int lane = t & 31;

    // freq weights
    if (t < 8) {
        float lim = (float)(t + 1) / 9.0f;
        float w = (fu[0] - lim) * 9.0f;
        g_zall[1600 + t] = fminf(fmaxf(w, 0.0f), 1.0f);
    }
    // zero z4 padding cols (j=4..7)
    if (t < 64 && (t & 7) >= 4) g_zall[1536 + t] = 0.0f;

    // per-batch cond biases via warp reductions: warp w -> (b, j)
    if (warp < 512) {
        const int b = warp >> 6, j = warp & 63;
        const float* cb = c + b * 128;
        float a1 = 0.f, a2 = 0.f, a3 = 0.f;
#pragma unroll
        for (int q = 0; q < 4; q++) {
            int k = lane + q * 32;
            float cv = cb[k];
            a1 = fmaf(cv, __ldg(w1 + j * 160 + 32 + k), a1);
            a2 = fmaf(cv, __ldg(w2 + j * 192 + 64 + k), a2);
            a3 = fmaf(cv, __ldg(w3 + j * 192 + 64 + k), a3);
        }
#pragma unroll
        for (int off = 16; off; off >>= 1) {
            a1 += __shfl_xor_sync(0xffffffffu, a1, off);
            a2 += __shfl_xor_sync(0xffffffffu, a2, off);
            a3 += __shfl_xor_sync(0xffffffffu, a3, off);
        }
        if (lane == 0) {
            g_zall[warp]        = b1[j] + S1 * a1;
            g_zall[512 + warp]  = b2[j] + S2 * a2;
            g_zall[1024 + warp] = b3[j] + S2 * a3;
        }
    }
    // z4: 32 warps -> (b, j) with j<4
    if (warp < 32) {
        const int b = warp >> 2, j = warp & 3;
        const float* cb = c + b * 128;
        float a4 = 0.f;
#pragma unroll
        for (int q = 0; q < 4; q++) {
            int k = lane + q * 32;
            a4 = fmaf(cb[k], __ldg(w4 + j * 192 + 64 + k), a4);
        }
#pragma unroll
        for (int off = 16; off; off >>= 1) a4 += __shfl_xor_sync(0xffffffffu, a4, off);
        if (lane == 0) g_zall[1536 + b * 8 + j] = b4[j] + S2 * a4;
    }

    // weight fragments (5376 hi/lo slot pairs)
    for (int s = t; s < 5376; s += stride) {
        int layer, rel, Hoff, Loff, KT;
        if (s < 1024)      { layer = 1; rel = s;        Hoff = F1H_OFF; Loff = F1L_OFF; KT = 2; }
        else if (s < 3072) { layer = 2; rel = s - 1024; Hoff = F2H_OFF; Loff = F2L_OFF; KT = 4; }
        else if (s < 5120) { layer = 3; rel = s - 3072; Hoff = F3H_OFF; Loff = F3L_OFF; KT = 4; }
        else               { layer = 4; rel = s - 5120; Hoff = F4H_OFF; Loff = F4L_OFF; KT = 4; }
        int reg  = rel & 1;
        int ln   = (rel >> 1) & 31;
        int tk   = (rel >> 6) % KT;
        int nt   = (rel >> 6) / KT;
        int gg = ln >> 2, cc = ln & 3;
        int n = nt * 8 + gg;
        int k0 = tk * 16 + 2 * cc + (reg ? 8 : 0);
        float v0, v1;
        if (layer == 1)      { v0 = w1[n * 160 + k0] * S1; v1 = w1[n * 160 + k0 + 1] * S1; }
        else if (layer == 2) { v0 = w2[n * 192 + k0] * S2; v1 = w2[n * 192 + k0 + 1] * S2; }
        else if (layer == 3) { v0 = w3[n * 192 + k0] * S2; v1 = w3[n * 192 + k0 + 1] * S2; }
        else { v0 = (n < 4) ? w4[n * 192 + k0] * S2 : 0.0f;
               v1 = (n < 4) ? w4[n * 192 + k0 + 1] * S2 : 0.0f; }
        uint32_t hw, lw;
        split2(v0, v1, hw, lw);
        g_wfrag[Hoff + rel] = hw;
        g_wfrag[Loff + rel] = lw;
    }
}

// ---------------- per-layer mma (weights from smem fragment arrays) ----------------
template<int KT>
__device__ __forceinline__ void layer_mma(float C[2][8][4],
                                          const uint32_t Ah[2][4][4],
                                          const uint32_t Al[2][4][4],
                                          const char* wh, const char* wl, int lane)
{
#pragma unroll
    for (int n = 0; n < 8; n++) {
        uint2 bh[KT], bl[KT];
#pragma unroll
        for (int kt = 0; kt < KT; kt++) {
            int off = ((n * KT + kt) * 32 + lane) * 8;
            bh[kt] = *(const uint2*)(wh + off);
            bl[kt] = *(const uint2*)(wl + off);
        }
#pragma unroll
        for (int m = 0; m < 2; m++)
#pragma unroll
            for (int kt = 0; kt < KT; kt++) {
                mma16816(C[m][n], Ah[m][kt], (const uint32_t*)&bh[kt]);
                mma16816(C[m][n], Ah[m][kt], (const uint32_t*)&bl[kt]);
                mma16816(C[m][n], Al[m][kt], (const uint32_t*)&bh[kt]);
            }
    }
}

// C (post-layer) -> next-layer A fragments, with bias + lrelu + hi/lo split
__device__ __forceinline__ void epilogue(const float C[2][8][4], const float* z, int c,
                                         uint32_t Ah[2][4][4], uint32_t Al[2][4][4])
{
#pragma unroll
    for (int kt = 0; kt < 4; kt++) {
        const int n0 = 2 * kt, n1 = 2 * kt + 1;
        float2 z0 = *(const float2*)(z + n0 * 8 + 2 * c);
        float2 z1 = *(const float2*)(z + n1 * 8 + 2 * c);
#pragma unroll
        for (int m = 0; m < 2; m++) {
            split2(actf(C[m][n0][0] + z0.x), actf(C[m][n0][1] + z0.y), Ah[m][kt][0], Al[m][kt][0]);
            split2(actf(C[m][n0][2] + z0.x), actf(C[m][n0][3] + z0.y), Ah[m][kt][1], Al[m][kt][1]);
            split2(actf(C[m][n1][0] + z1.x), actf(C[m][n1][1] + z1.y), Ah[m][kt][2], Al[m][kt][2]);
            split2(actf(C[m][n1][2] + z1.x), actf(C[m][n1][3] + z1.y), Ah[m][kt][3], Al[m][kt][3]);
        }
    }
}

// ---------------- main kernel ----------------
__global__ __launch_bounds__(TPB, 3) void decoder_kernel(const float* __restrict__ coords,
                                                         float* __restrict__ out)
{
    extern __shared__ __align__(16) char sm[];
    const int tid = threadIdx.x;
    const int wid = tid >> 5;
    const int lane = tid & 31;
    const int g = lane >> 2, c = lane & 3;

    // ---- stage weights + z/fw into shared (once per CTA) ----
    {
        const uint4* src = (const uint4*)g_wfrag;
        uint4* dst = (uint4*)(sm + SW_BASE);
        for (int i = tid; i < WFRAG_U32 / 4; i += TPB) dst[i] = src[i];
        const float4* zs = (const float4*)g_zall;
        float4* zd = (float4*)(sm + SM_ZBASE);
        for (int i = tid; i < 1608 / 4; i += TPB) zd[i] = zs[i];
    }
    __syncthreads();

    const float* s_fw = (const float*)(sm + SM_ZBASE) + 1600;
    uint32_t* s_eh = (uint32_t*)(sm + SM_EH);
    uint32_t* s_el = (uint32_t*)(sm + SM_EL);
    float* s_mask = (float*)(sm + SM_MASK);

    for (int chunk = blockIdx.x * 4 + wid; chunk < NCHUNKS; chunk += NWARPS_TOTAL) {
        const int pixbase = chunk * 32;
        const int batch = pixbase >> 16;

        // ---- embedding: each lane computes its pixel, writes hi/lo bf16 rows ----
        {
            const int p = pixbase + lane;
            const float2 xy = ((const float2*)coords)[p];
            float sx, cx, sy, cy;
            sincosf(xy.x * 0.1f, &sx, &cx);
            sincosf(xy.y * 0.1f, &sy, &cy);
            float r = sqrtf(fmaf(xy.x, xy.x, xy.y * xy.y));
            s_mask[wid * 32 + lane] = 1.0f - tanhf(fmaxf(r - 1.0f, 0.0f));

            float e[32];
#pragma unroll
            for (int i = 0; i < 8; i++) {
                float w = s_fw[i];
                e[4 * i + 0] = sx * w;
                e[4 * i + 1] = sy * w;
                e[4 * i + 2] = cx * w;
                e[4 * i + 3] = cy * w;
                if (i < 7) {
                    float nsx = 2.0f * sx * cx;
                    float ncx = fmaf(-2.0f * sx, sx, 1.0f);
                    float nsy = 2.0f * sy * cy;
                    float ncy = fmaf(-2.0f * sy, sy, 1.0f);
                    sx = nsx; cx = ncx; sy = nsy; cy = ncy;
                }
            }
            uint32_t* ehr = s_eh + (wid * 32 + lane) * 17;
            uint32_t* elr = s_el + (wid * 32 + lane) * 17;
#pragma unroll
            for (int q = 0; q < 16; q++) {
                uint32_t hw, lw;
                split2(e[2 * q], e[2 * q + 1], hw, lw);
                ehr[q] = hw;
                elr[q] = lw;
            }
        }
        __syncwarp();

        // ---- load layer-1 A fragments from smem ----
        uint32_t Ah[2][4][4], Al[2][4][4];
#pragma unroll
        for (int m = 0; m < 2; m++) {
            const int r0 = wid * 32 + m * 16 + g;
            const uint32_t* eh0 = s_eh + r0 * 17;
            const uint32_t* eh1 = eh0 + 8 * 17;
            const uint32_t* el0 = s_el + r0 * 17;
            const uint32_t* el1 = el0 + 8 * 17;
#pragma unroll
            for (int kt = 0; kt < 2; kt++) {
                Ah[m][kt][0] = eh0[kt * 8 + c];
                Ah[m][kt][1] = eh1[kt * 8 + c];
                Ah[m][kt][2] = eh0[kt * 8 + c + 4];
                Ah[m][kt][3] = eh1[kt * 8 + c + 4];
                Al[m][kt][0] = el0[kt * 8 + c];
                Al[m][kt][1] = el1[kt * 8 + c];
                Al[m][kt][2] = el0[kt * 8 + c + 4];
                Al[m][kt][3] = el1[kt * 8 + c + 4];
            }
        }
        __syncwarp();

        float C[2][8][4];

        // ---- layer 1 (KT=2) ----
#pragma unroll
        for (int m = 0; m < 2; m++)
#pragma unroll
            for (int n = 0; n < 8; n++)
#pragma unroll
                for (int q = 0; q < 4; q++) C[m][n][q] = 0.0f;
        layer_mma<2>(C, Ah, Al, sm + F1H_OFF * 4, sm + F1L_OFF * 4, lane);
        epilogue(C, (const float*)(sm + SM_ZBASE) + batch * 64, c, Ah, Al);

        // ---- layer 2 (KT=4) ----
#pragma unroll
        for (int m = 0; m < 2; m++)
#pragma unroll
            for (int n = 0; n < 8; n++)
#pragma unroll
                for (int q = 0; q < 4; q++) C[m][n][q] = 0.0f;
        layer_mma<4>(C, Ah, Al, sm + F2H_OFF * 4, sm + F2L_OFF * 4, lane);
        epilogue(C, (const float*)(sm + SM_ZBASE) + 512 + batch * 64, c, Ah, Al);

        // ---- layer 3 (KT=4) ----
#pragma unroll
        for (int m = 0; m < 2; m++)
#pragma unroll
            for (int n = 0; n < 8; n++)
#pragma unroll
                for (int q = 0; q < 4; q++) C[m][n][q] = 0.0f;
        layer_mma<4>(C, Ah, Al, sm + F3H_OFF * 4, sm + F3L_OFF * 4, lane);
        epilogue(C, (const float*)(sm + SM_ZBASE) + 1024 + batch * 64, c, Ah, Al);

        // ---- layer 4: single n8 tile (cols 0..3 real) ----
        float C4[2][4];
#pragma unroll
        for (int m = 0; m < 2; m++)
#pragma unroll
            for (int q = 0; q < 4; q++) C4[m][q] = 0.0f;
#pragma unroll
        for (int kt = 0; kt < 4; kt++) {
            const int off = (kt * 32 + lane) * 8;
            uint2 bh = *(const uint2*)(sm + F4H_OFF * 4 + off);
            uint2 bl = *(const uint2*)(sm + F4L_OFF * 4 + off);
#pragma unroll
            for (int m = 0; m < 2; m++) {
                mma16816(C4[m], Ah[m][kt], (const uint32_t*)&bh);
                mma16816(C4[m], Ah[m][kt], (const uint32_t*)&bl);
                mma16816(C4[m], Al[m][kt], (const uint32_t*)&bh);
            }
        }

        // ---- output: threads c<2 hold real cols (2c, 2c+1) ----
        if (c < 2) {
            const float* z4 = (const float*)(sm + SM_ZBASE) + 1536 + batch * 8;
            const float z40 = z4[2 * c], z41 = z4[2 * c + 1];
#pragma unroll
            for (int m = 0; m < 2; m++) {
                const int rloc = wid * 32 + m * 16 + g;
                const int pix0 = pixbase + m * 16 + g;
                const float mk0 = s_mask[rloc];
                const float mk1 = s_mask[rloc + 8];
                float2 o0, o1;
                o0.x = (C4[m][0] + z40) * mk0;
                o0.y = (C4[m][1] + z41) * mk0;
                o1.x = (C4[m][2] + z40) * mk1;
                o1.y = (C4[m][3] + z41) * mk1;
                *(float2*)(out + pix0 * 4 + 2 * c) = o0;
                *(float2*)(out + (pix0 + 8) * 4 + 2 * c) = o1;
            }
        }
    }
}

// ---------------- launch ----------------
extern "C" void kernel_launch(void* const* d_in, const int* in_sizes, int n_in,
                              void* d_out, int out_size)
{
    const float* coords = (const float*)d_in[0];
    const float* c      = (const float*)d_in[1];
    const float* fu     = (const float*)d_in[2];
    const float* w1     = (const float*)d_in[3];
    const float* b1     = (const float*)d_in[4];
    const float* w2     = (const float*)d_in[5];
    const float* b2     = (const float*)d_in[6];
    const float* w3     = (const float*)d_in[7];
    const float* b3     = (const float*)d_in[8];
    const float* w4     = (const float*)d_in[9];
    const float* b4     = (const float*)d_in[10];
    float* out = (float*)d_out;

    cudaFuncSetAttribute(decoder_kernel, cudaFuncAttributeMaxDynamicSharedMemorySize, SM_TOTAL);
    prep_kernel<<<64, 256>>>(c, fu, w1, b1, w2, b2, w3, b3, w4, b4);
    decoder_kernel<<<GRID_MAIN, TPB, SM_TOTAL>>>(coords, out);
}

// round 5
// speedup vs baseline: 10.5653x; 1.6049x over previous
#include <cuda_runtime.h>
#include <cuda_fp16.h>
#include <cstdint>
#include <math.h>

#define S1 0.07905694150420948f   // 1/sqrt(160)
#define S2 0.07216878364870323f   // 1/sqrt(192)
#define NCHUNKS 16384             // 524288 px / 32 per warp-chunk
#define GRID_MAIN 456             // 3 CTAs/SM x 152 SMs
#define TPB 128
#define NWARPS_TOTAL (GRID_MAIN * (TPB / 32))

// lrelu(t)*sqrt(2) = A_*t + B_*|t|,  A_=0.6*sqrt2, B_=0.4*sqrt2
#define ACT_A 0.84852813742385703f
#define ACT_B 0.56568542494923801f

// ---- weight fragment layout (u32 indices inside g_wfrag / smem) ----
// per frag-slot: ((ntile*KT + kt)*32 + lane)*2 + reg
#define F1H_OFF 0        // [8 ntile][2 kt][32 lane][2 reg] = 1024 u32
#define F1L_OFF 1024
#define F2H_OFF 2048     // [8][4][32][2] = 2048 u32
#define F2L_OFF 4096
#define F3H_OFF 6144
#define F3L_OFF 8192
#define F4H_OFF 10240    // [1][4][32][2] = 256 u32
#define F4L_OFF 10496
#define WFRAG_U32 10752

// ---- shared memory byte offsets ----
#define SW_BASE   0               // weight frags: 43008 B
#define SM_ZBASE  43008           // 1608 floats: z1[512] z2[512] z3[512] z4[64] fw[8]
#define SM_EH     49440           // 128 rows x 17 u32 (fp16x2 embedding)
#define SM_TOTAL  58144

// ---- device globals (prep outputs) ----
__device__ __align__(16) uint32_t g_wfrag[WFRAG_U32];
__device__ __align__(16) float    g_zall[1608];

// ---------------- helpers ----------------
__device__ __forceinline__ void mma16816(float* c, const uint32_t* a, const uint32_t* b) {
    asm volatile(
        "mma.sync.aligned.m16n8k16.row.col.f32.f16.f16.f32 "
        "{%0,%1,%2,%3}, {%4,%5,%6,%7}, {%8,%9}, {%0,%1,%2,%3};"
        : "+f"(c[0]), "+f"(c[1]), "+f"(c[2]), "+f"(c[3])
        : "r"(a[0]), "r"(a[1]), "r"(a[2]), "r"(a[3]), "r"(b[0]), "r"(b[1]));
}

// pack two fp32 -> fp16x2 word (low half = v0)
__device__ __forceinline__ uint32_t packh2(float v0, float v1) {
    __half2 h = __floats2half2_rn(v0, v1);
    return *(uint32_t*)&h;
}

// fp16 hi/lo split of a pair
__device__ __forceinline__ void split2h(float v0, float v1, uint32_t& hi, uint32_t& lo) {
    __half2 h = __floats2half2_rn(v0, v1);
    float h0 = __half2float(__low2half(h));
    float h1 = __half2float(__high2half(h));
    __half2 l = __floats2half2_rn(v0 - h0, v1 - h1);
    hi = *(uint32_t*)&h;
    lo = *(uint32_t*)&l;
}

__device__ __forceinline__ float actf(float t) {
    return fmaf(fabsf(t), ACT_B, ACT_A * t);
}

// ---------------- prep kernel ----------------
__global__ void prep_kernel(const float* __restrict__ c, const float* __restrict__ fu,
                            const float* __restrict__ w1, const float* __restrict__ b1,
                            const float* __restrict__ w2, const float* __restrict__ b2,
                            const float* __restrict__ w3, const float* __restrict__ b3,
                            const float* __restrict__ w4, const float* __restrict__ b4)
{
    const int t = blockIdx.x * blockDim.x + threadIdx.x;
    const int stride = gridDim.x * blockDim.x;
    const int warp = t >> 5;
    const int lane = t & 31;

    // freq weights
    if (t < 8) {
        float lim = (float)(t + 1) / 9.0f;
        float w = (fu[0] - lim) * 9.0f;
        g_zall[1600 + t] = fminf(fmaxf(w, 0.0f), 1.0f);
    }
    // zero z4 padding cols (j=4..7)
    if (t < 64 && (t & 7) >= 4) g_zall[1536 + t] = 0.0f;

    // per-batch cond biases via warp reductions: warp w -> (b, j)
    if (warp < 512) {
        const int b = warp >> 6, j = warp & 63;
        const float* cb = c + b * 128;
        float a1 = 0.f, a2 = 0.f, a3 = 0.f;
#pragma unroll
        for (int q = 0; q < 4; q++) {
            int k = lane + q * 32;
            float cv = cb[k];
            a1 = fmaf(cv, __ldg(w1 + j * 160 + 32 + k), a1);
            a2 = fmaf(cv, __ldg(w2 + j * 192 + 64 + k), a2);
            a3 = fmaf(cv, __ldg(w3 + j * 192 + 64 + k), a3);
        }
#pragma unroll
        for (int off = 16; off; off >>= 1) {
            a1 += __shfl_xor_sync(0xffffffffu, a1, off);
            a2 += __shfl_xor_sync(0xffffffffu, a2, off);
            a3 += __shfl_xor_sync(0xffffffffu, a3, off);
        }
        if (lane == 0) {
            g_zall[warp]        = b1[j] + S1 * a1;
            g_zall[512 + warp]  = b2[j] + S2 * a2;
            g_zall[1024 + warp] = b3[j] + S2 * a3;
        }
    }
    // z4: 32 warps -> (b, j) with j<4
    if (warp < 32) {
        const int b = warp >> 2, j = warp & 3;
        const float* cb = c + b * 128;
        float a4 = 0.f;
#pragma unroll
        for (int q = 0; q < 4; q++) {
            int k = lane + q * 32;
            a4 = fmaf(cb[k], __ldg(w4 + j * 192 + 64 + k), a4);
        }
#pragma unroll
        for (int off = 16; off; off >>= 1) a4 += __shfl_xor_sync(0xffffffffu, a4, off);
        if (lane == 0) g_zall[1536 + b * 8 + j] = b4[j] + S2 * a4;
    }

    // weight fragments (5376 hi/lo slot pairs), fp16 split
    for (int s = t; s < 5376; s += stride) {
        int layer, rel, Hoff, Loff, KT;
        if (s < 1024)      { layer = 1; rel = s;        Hoff = F1H_OFF; Loff = F1L_OFF; KT = 2; }
        else if (s < 3072) { layer = 2; rel = s - 1024; Hoff = F2H_OFF; Loff = F2L_OFF; KT = 4; }
        else if (s < 5120) { layer = 3; rel = s - 3072; Hoff = F3H_OFF; Loff = F3L_OFF; KT = 4; }
        else               { layer = 4; rel = s - 5120; Hoff = F4H_OFF; Loff = F4L_OFF; KT = 4; }
        int reg  = rel & 1;
        int ln   = (rel >> 1) & 31;
        int tk   = (rel >> 6) % KT;
        int nt   = (rel >> 6) / KT;
        int gg = ln >> 2, cc = ln & 3;
        int n = nt * 8 + gg;
        int k0 = tk * 16 + 2 * cc + (reg ? 8 : 0);
        float v0, v1;
        if (layer == 1)      { v0 = w1[n * 160 + k0] * S1; v1 = w1[n * 160 + k0 + 1] * S1; }
        else if (layer == 2) { v0 = w2[n * 192 + k0] * S2; v1 = w2[n * 192 + k0 + 1] * S2; }
        else if (layer == 3) { v0 = w3[n * 192 + k0] * S2; v1 = w3[n * 192 + k0 + 1] * S2; }
        else { v0 = (n < 4) ? w4[n * 192 + k0] * S2 : 0.0f;
               v1 = (n < 4) ? w4[n * 192 + k0 + 1] * S2 : 0.0f; }
        uint32_t hw, lw;
        split2h(v0, v1, hw, lw);
        g_wfrag[Hoff + rel] = hw;
        g_wfrag[Loff + rel] = lw;
    }
}

// ---------------- per-layer mma (2-pass: A fp16, B hi+lo fp16) ----------------
template<int KT>
__device__ __forceinline__ void layer_mma(float C[2][8][4],
                                          const uint32_t Ah[2][4][4],
                                          const char* wh, const char* wl, int lane)
{
#pragma unroll
    for (int n = 0; n < 8; n++) {
        uint2 bh[KT], bl[KT];
#pragma unroll
        for (int kt = 0; kt < KT; kt++) {
            int off = ((n * KT + kt) * 32 + lane) * 8;
            bh[kt] = *(const uint2*)(wh + off);
            bl[kt] = *(const uint2*)(wl + off);
        }
#pragma unroll
        for (int m = 0; m < 2; m++)
#pragma unroll
            for (int kt = 0; kt < KT; kt++) {
                mma16816(C[m][n], Ah[m][kt], (const uint32_t*)&bh[kt]);
                mma16816(C[m][n], Ah[m][kt], (const uint32_t*)&bl[kt]);
            }
    }
}

// C (post-layer) -> next-layer A fragments, with bias + lrelu + fp16 pack
__device__ __forceinline__ void epilogue(const float C[2][8][4], const float* z, int c,
                                         uint32_t Ah[2][4][4])
{
#pragma unroll
    for (int kt = 0; kt < 4; kt++) {
        const int n0 = 2 * kt, n1 = 2 * kt + 1;
        float2 z0 = *(const float2*)(z + n0 * 8 + 2 * c);
        float2 z1 = *(const float2*)(z + n1 * 8 + 2 * c);
#pragma unroll
        for (int m = 0; m < 2; m++) {
            Ah[m][kt][0] = packh2(actf(C[m][n0][0] + z0.x), actf(C[m][n0][1] + z0.y));
            Ah[m][kt][1] = packh2(actf(C[m][n0][2] + z0.x), actf(C[m][n0][3] + z0.y));
            Ah[m][kt][2] = packh2(actf(C[m][n1][0] + z1.x), actf(C[m][n1][1] + z1.y));
            Ah[m][kt][3] = packh2(actf(C[m][n1][2] + z1.x), actf(C[m][n1][3] + z1.y));
        }
    }
}

// ---------------- main kernel ----------------
__global__ __launch_bounds__(TPB, 3) void decoder_kernel(const float* __restrict__ coords,
                                                         float* __restrict__ out)
{
    extern __shared__ __align__(16) char sm[];
    const int tid = threadIdx.x;
    const int wid = tid >> 5;
    const int lane = tid & 31;
    const int g = lane >> 2, c = lane & 3;

    // ---- stage weights + z/fw into shared (once per CTA) ----
    {
        const uint4* src = (const uint4*)g_wfrag;
        uint4* dst = (uint4*)(sm + SW_BASE);
        for (int i = tid; i < WFRAG_U32 / 4; i += TPB) dst[i] = src[i];
        const float4* zs = (const float4*)g_zall;
        float4* zd = (float4*)(sm + SM_ZBASE);
        for (int i = tid; i < 1608 / 4; i += TPB) zd[i] = zs[i];
    }
    __syncthreads();

    const float* s_fw = (const float*)(sm + SM_ZBASE) + 1600;
    uint32_t* s_eh = (uint32_t*)(sm + SM_EH);

    for (int chunk = blockIdx.x * 4 + wid; chunk < NCHUNKS; chunk += NWARPS_TOTAL) {
        const int pixbase = chunk * 32;
        const int batch = chunk >> 11;

        // ---- embedding: each lane computes its pixel, writes fp16x2 row ----
        float maskv;
        {
            const int p = pixbase + lane;
            const float2 xy = ((const float2*)coords)[p];
            float sx, cx, sy, cy;
            __sincosf(xy.x * 0.1f, &sx, &cx);
            __sincosf(xy.y * 0.1f, &sy, &cy);
            float r = sqrtf(fmaf(xy.x, xy.x, xy.y * xy.y));
            float u = fmaxf(r - 1.0f, 0.0f);
            // 1 - tanh(u) == 2 / (exp(2u) + 1)
            maskv = __fdividef(2.0f, __expf(2.0f * u) + 1.0f);

            float e[32];
#pragma unroll
            for (int i = 0; i < 8; i++) {
                float w = s_fw[i];
                e[4 * i + 0] = sx * w;
                e[4 * i + 1] = sy * w;
                e[4 * i + 2] = cx * w;
                e[4 * i + 3] = cy * w;
                if (i < 7) {
                    float nsx = 2.0f * sx * cx;
                    float ncx = fmaf(-2.0f * sx, sx, 1.0f);
                    float nsy = 2.0f * sy * cy;
                    float ncy = fmaf(-2.0f * sy, sy, 1.0f);
                    sx = nsx; cx = ncx; sy = nsy; cy = ncy;
                }
            }
            uint32_t* ehr = s_eh + (wid * 32 + lane) * 17;
#pragma unroll
            for (int q = 0; q < 16; q++) ehr[q] = packh2(e[2 * q], e[2 * q + 1]);
        }
        __syncwarp();

        // ---- load layer-1 A fragments from smem ----
        uint32_t Ah[2][4][4];
#pragma unroll
        for (int m = 0; m < 2; m++) {
            const int r0 = wid * 32 + m * 16 + g;
            const uint32_t* eh0 = s_eh + r0 * 17;
            const uint32_t* eh1 = eh0 + 8 * 17;
#pragma unroll
            for (int kt = 0; kt < 2; kt++) {
                Ah[m][kt][0] = eh0[kt * 8 + c];
                Ah[m][kt][1] = eh1[kt * 8 + c];
                Ah[m][kt][2] = eh0[kt * 8 + c + 4];
                Ah[m][kt][3] = eh1[kt * 8 + c + 4];
            }
        }
        __syncwarp();

        float C[2][8][4];

        // ---- layer 1 (KT=2) ----
#pragma unroll
        for (int m = 0; m < 2; m++)
#pragma unroll
            for (int n = 0; n < 8; n++)
#pragma unroll
                for (int q = 0; q < 4; q++) C[m][n][q] = 0.0f;
        layer_mma<2>(C, Ah, sm + F1H_OFF * 4, sm + F1L_OFF * 4, lane);
        epilogue(C, (const float*)(sm + SM_ZBASE) + batch * 64, c, Ah);

        // ---- layer 2 (KT=4) ----
#pragma unroll
        for (int m = 0; m < 2; m++)
#pragma unroll
            for (int n = 0; n < 8; n++)
#pragma unroll
                for (int q = 0; q < 4; q++) C[m][n][q] = 0.0f;
        layer_mma<4>(C, Ah, sm + F2H_OFF * 4, sm + F2L_OFF * 4, lane);
        epilogue(C, (const float*)(sm + SM_ZBASE) + 512 + batch * 64, c, Ah);

        // ---- layer 3 (KT=4) ----
#pragma unroll
        for (int m = 0; m < 2; m++)
#pragma unroll
            for (int n = 0; n < 8; n++)
#pragma unroll
                for (int q = 0; q < 4; q++) C[m][n][q] = 0.0f;
        layer_mma<4>(C, Ah, sm + F3H_OFF * 4, sm + F3L_OFF * 4, lane);
        epilogue(C, (const float*)(sm + SM_ZBASE) + 1024 + batch * 64, c, Ah);

        // ---- layer 4: single n8 tile (cols 0..3 real) ----
        float C4[2][4];
#pragma unroll
        for (int m = 0; m < 2; m++)
#pragma unroll
            for (int q = 0; q < 4; q++) C4[m][q] = 0.0f;
#pragma unroll
        for (int kt = 0; kt < 4; kt++) {
            const int off = (kt * 32 + lane) * 8;
            uint2 bh = *(const uint2*)(sm + F4H_OFF * 4 + off);
            uint2 bl = *(const uint2*)(sm + F4L_OFF * 4 + off);
#pragma unroll
            for (int m = 0; m < 2; m++) {
                mma16816(C4[m], Ah[m][kt], (const uint32_t*)&bh);
                mma16816(C4[m], Ah[m][kt], (const uint32_t*)&bl);
            }
        }

        // ---- masks via shfl (all lanes participate) ----
        float mk[2][2];
#pragma unroll
        for (int m = 0; m < 2; m++) {
            mk[m][0] = __shfl_sync(0xffffffffu, maskv, m * 16 + g);
            mk[m][1] = __shfl_sync(0xffffffffu, maskv, m * 16 + 8 + g);
        }

        // ---- output: threads c<2 hold real cols (2c, 2c+1) ----
        if (c < 2) {
            const float* z4 = (const float*)(sm + SM_ZBASE) + 1536 + batch * 8;
            const float z40 = z4[2 * c], z41 = z4[2 * c + 1];
#pragma unroll
            for (int m = 0; m < 2; m++) {
                const int pix0 = pixbase + m * 16 + g;
                float2 o0, o1;
                o0.x = (C4[m][0] + z40) * mk[m][0];
                o0.y = (C4[m][1] + z41) * mk[m][0];
                o1.x = (C4[m][2] + z40) * mk[m][1];
                o1.y = (C4[m][3] + z41) * mk[m][1];
                *(float2*)(out + pix0 * 4 + 2 * c) = o0;
                *(float2*)(out + (pix0 + 8) * 4 + 2 * c) = o1;
            }
        }
    }
}

// ---------------- launch ----------------
extern "C" void kernel_launch(void* const* d_in, const int* in_sizes, int n_in,
                              void* d_out, int out_size)
{
    const float* coords = (const float*)d_in[0];
    const float* c      = (const float*)d_in[1];
    const float* fu     = (const float*)d_in[2];
    const float* w1     = (const float*)d_in[3];
    const float* b1     = (const float*)d_in[4];
    const float* w2     = (const float*)d_in[5];
    const float* b2     = (const float*)d_in[6];
    const float* w3     = (const float*)d_in[7];
    const float* b3     = (const float*)d_in[8];
    const float* w4     = (const float*)d_in[9];
    const float* b4     = (const float*)d_in[10];
    float* out = (float*)d_out;

    cudaFuncSetAttribute(decoder_kernel, cudaFuncAttributeMaxDynamicSharedMemorySize, SM_TOTAL);
    prep_kernel<<<64, 256>>>(c, fu, w1, b1, w2, b2, w3, b3, w4, b4);
    decoder_kernel<<<GRID_MAIN, TPB, SM_TOTAL>>>(coords, out);
}

// round 6
// speedup vs baseline: 15.1133x; 1.4305x over previous
#include <cuda_runtime.h>
#include <cuda_fp16.h>
#include <cstdint>
#include <math.h>

#define S1 0.07905694150420948f   // 1/sqrt(160)
#define S2 0.07216878364870323f   // 1/sqrt(192)
#define NCHUNKS 16384             // 524288 px / 32 per warp-chunk
#define GRID_MAIN 608             // 4 CTAs/SM x 152 SMs
#define TPB 128
#define NWARPS_TOTAL (GRID_MAIN * (TPB / 32))

// lrelu(t)*sqrt(2) = A_*t + B_*|t|,  A_=0.6*sqrt2, B_=0.4*sqrt2
#define ACT_A 0.84852813742385703f
#define ACT_B 0.56568542494923801f

// ---- weight fragment layout (u32 indices inside g_wfrag / smem) ----
// per frag-slot: ((ntile*KT + kt)*32 + lane)*2 + reg
#define F1_OFF 0        // [8 ntile][2 kt][32 lane][2 reg] = 1024 u32
#define F2_OFF 1024     // [8][4][32][2] = 2048 u32
#define F3_OFF 3072
#define F4_OFF 5120     // [1][4][32][2] = 256 u32
#define WFRAG_U32 5376

// ---- shared memory byte offsets ----
#define SW_BASE   0               // weight frags: 21504 B
#define SM_ZBASE  21504           // 1608 floats: z1[512] z2[512] z3[512] z4[64] fw[8]
#define SM_EH     27936           // 128 rows x 17 u32 (fp16x2 embedding)
#define SM_TOTAL  36640

// ---- device globals (prep outputs) ----
__device__ __align__(16) uint32_t g_wfrag[WFRAG_U32];
__device__ __align__(16) float    g_zall[1608];

// ---------------- helpers ----------------
__device__ __forceinline__ void mma16816(float* c, const uint32_t* a, const uint32_t* b) {
    asm volatile(
        "mma.sync.aligned.m16n8k16.row.col.f32.f16.f16.f32 "
        "{%0,%1,%2,%3}, {%4,%5,%6,%7}, {%8,%9}, {%0,%1,%2,%3};"
        : "+f"(c[0]), "+f"(c[1]), "+f"(c[2]), "+f"(c[3])
        : "r"(a[0]), "r"(a[1]), "r"(a[2]), "r"(a[3]), "r"(b[0]), "r"(b[1]));
}

// pack two fp32 -> fp16x2 word (low half = v0)
__device__ __forceinline__ uint32_t packh2(float v0, float v1) {
    __half2 h = __floats2half2_rn(v0, v1);
    return *(uint32_t*)&h;
}

__device__ __forceinline__ float actf(float t) {
    return fmaf(fabsf(t), ACT_B, ACT_A * t);
}

// ---------------- prep kernel ----------------
__global__ void prep_kernel(const float* __restrict__ c, const float* __restrict__ fu,
                            const float* __restrict__ w1, const float* __restrict__ b1,
                            const float* __restrict__ w2, const float* __restrict__ b2,
                            const float* __restrict__ w3, const float* __restrict__ b3,
                            const float* __restrict__ w4, const float* __restrict__ b4)
{
    const int t = blockIdx.x * blockDim.x + threadIdx.x;
    const int stride = gridDim.x * blockDim.x;
    const int warp = t >> 5;
    const int lane = t & 31;

    // freq weights
    if (t < 8) {
        float lim = (float)(t + 1) / 9.0f;
        float w = (fu[0] - lim) * 9.0f;
        g_zall[1600 + t] = fminf(fmaxf(w, 0.0f), 1.0f);
    }
    // zero z4 padding cols (j=4..7)
    if (t < 64 && (t & 7) >= 4) g_zall[1536 + t] = 0.0f;

    // per-batch cond biases via warp reductions: warp w -> (b, j)
    if (warp < 512) {
        const int b = warp >> 6, j = warp & 63;
        const float* cb = c + b * 128;
        float a1 = 0.f, a2 = 0.f, a3 = 0.f;
#pragma unroll
        for (int q = 0; q < 4; q++) {
            int k = lane + q * 32;
            float cv = cb[k];
            a1 = fmaf(cv, __ldg(w1 + j * 160 + 32 + k), a1);
            a2 = fmaf(cv, __ldg(w2 + j * 192 + 64 + k), a2);
            a3 = fmaf(cv, __ldg(w3 + j * 192 + 64 + k), a3);
        }
#pragma unroll
        for (int off = 16; off; off >>= 1) {
            a1 += __shfl_xor_sync(0xffffffffu, a1, off);
            a2 += __shfl_xor_sync(0xffffffffu, a2, off);
            a3 += __shfl_xor_sync(0xffffffffu, a3, off);
        }
        if (lane == 0) {
            g_zall[warp]        = b1[j] + S1 * a1;
            g_zall[512 + warp]  = b2[j] + S2 * a2;
            g_zall[1024 + warp] = b3[j] + S2 * a3;
        }
    }
    // z4: 32 warps -> (b, j) with j<4
    if (warp < 32) {
        const int b = warp >> 2, j = warp & 3;
        const float* cb = c + b * 128;
        float a4 = 0.f;
#pragma unroll
        for (int q = 0; q < 4; q++) {
            int k = lane + q * 32;
            a4 = fmaf(cb[k], __ldg(w4 + j * 192 + 64 + k), a4);
        }
#pragma unroll
        for (int off = 16; off; off >>= 1) a4 += __shfl_xor_sync(0xffffffffu, a4, off);
        if (lane == 0) g_zall[1536 + b * 8 + j] = b4[j] + S2 * a4;
    }

    // weight fragments (5376 fp16x2 slots)
    for (int s = t; s < 5376; s += stride) {
        int layer, rel, Foff, KT;
        if (s < 1024)      { layer = 1; rel = s;        Foff = F1_OFF; KT = 2; }
        else if (s < 3072) { layer = 2; rel = s - 1024; Foff = F2_OFF; KT = 4; }
        else if (s < 5120) { layer = 3; rel = s - 3072; Foff = F3_OFF; KT = 4; }
        else               { layer = 4; rel = s - 5120; Foff = F4_OFF; KT = 4; }
        int reg  = rel & 1;
        int ln   = (rel >> 1) & 31;
        int tk   = (rel >> 6) % KT;
        int nt   = (rel >> 6) / KT;
        int gg = ln >> 2, cc = ln & 3;
        int n = nt * 8 + gg;
        int k0 = tk * 16 + 2 * cc + (reg ? 8 : 0);
        float v0, v1;
        if (layer == 1)      { v0 = w1[n * 160 + k0] * S1; v1 = w1[n * 160 + k0 + 1] * S1; }
        else if (layer == 2) { v0 = w2[n * 192 + k0] * S2; v1 = w2[n * 192 + k0 + 1] * S2; }
        else if (layer == 3) { v0 = w3[n * 192 + k0] * S2; v1 = w3[n * 192 + k0 + 1] * S2; }
        else { v0 = (n < 4) ? w4[n * 192 + k0] * S2 : 0.0f;
               v1 = (n < 4) ? w4[n * 192 + k0 + 1] * S2 : 0.0f; }
        g_wfrag[Foff + rel] = packh2(v0, v1);
    }
}

// ---------------- per-layer mma (single-pass fp16) ----------------
template<int KT>
__device__ __forceinline__ void layer_mma(float C[2][8][4],
                                          const uint32_t Ah[2][4][4],
                                          const char* wf, int lane)
{
#pragma unroll
    for (int n = 0; n < 8; n++) {
        uint2 bh[KT];
#pragma unroll
        for (int kt = 0; kt < KT; kt++) {
            int off = ((n * KT + kt) * 32 + lane) * 8;
            bh[kt] = *(const uint2*)(wf + off);
        }
#pragma unroll
        for (int m = 0; m < 2; m++)
#pragma unroll
            for (int kt = 0; kt < KT; kt++)
                mma16816(C[m][n], Ah[m][kt], (const uint32_t*)&bh[kt]);
    }
}

// C (post-layer) -> next-layer A fragments, with bias + lrelu + fp16 pack
__device__ __forceinline__ void epilogue(const float C[2][8][4], const float* z, int c,
                                         uint32_t Ah[2][4][4])
{
#pragma unroll
    for (int kt = 0; kt < 4; kt++) {
        const int n0 = 2 * kt, n1 = 2 * kt + 1;
        float2 z0 = *(const float2*)(z + n0 * 8 + 2 * c);
        float2 z1 = *(const float2*)(z + n1 * 8 + 2 * c);
#pragma unroll
        for (int m = 0; m < 2; m++) {
            Ah[m][kt][0] = packh2(actf(C[m][n0][0] + z0.x), actf(C[m][n0][1] + z0.y));
            Ah[m][kt][1] = packh2(actf(C[m][n0][2] + z0.x), actf(C[m][n0][3] + z0.y));
            Ah[m][kt][2] = packh2(actf(C[m][n1][0] + z1.x), actf(C[m][n1][1] + z1.y));
            Ah[m][kt][3] = packh2(actf(C[m][n1][2] + z1.x), actf(C[m][n1][3] + z1.y));
        }
    }
}

// ---------------- main kernel ----------------
__global__ __launch_bounds__(TPB, 4) void decoder_kernel(const float* __restrict__ coords,
                                                         float* __restrict__ out)
{
    extern __shared__ __align__(16) char sm[];
    const int tid = threadIdx.x;
    const int wid = tid >> 5;
    const int lane = tid & 31;
    const int g = lane >> 2, c = lane & 3;

    // ---- stage weights + z/fw into shared (once per CTA) ----
    {
        const uint4* src = (const uint4*)g_wfrag;
        uint4* dst = (uint4*)(sm + SW_BASE);
        for (int i = tid; i < WFRAG_U32 / 4; i += TPB) dst[i] = src[i];
        const float4* zs = (const float4*)g_zall;
        float4* zd = (float4*)(sm + SM_ZBASE);
        for (int i = tid; i < 1608 / 4; i += TPB) zd[i] = zs[i];
    }
    __syncthreads();

    const float* s_fw = (const float*)(sm + SM_ZBASE) + 1600;
    uint32_t* s_eh = (uint32_t*)(sm + SM_EH);

    for (int chunk = blockIdx.x * 4 + wid; chunk < NCHUNKS; chunk += NWARPS_TOTAL) {
        const int pixbase = chunk * 32;
        const int batch = chunk >> 11;

        // ---- embedding: each lane computes its pixel, writes fp16x2 row ----
        float maskv;
        {
            const int p = pixbase + lane;
            const float2 xy = ((const float2*)coords)[p];
            float sx, cx, sy, cy;
            __sincosf(xy.x * 0.1f, &sx, &cx);
            __sincosf(xy.y * 0.1f, &sy, &cy);
            float r = sqrtf(fmaf(xy.x, xy.x, xy.y * xy.y));
            float u = fmaxf(r - 1.0f, 0.0f);
            // 1 - tanh(u) == 2 / (exp(2u) + 1)
            maskv = __fdividef(2.0f, __expf(2.0f * u) + 1.0f);

            float e[32];
#pragma unroll
            for (int i = 0; i < 8; i++) {
                float w = s_fw[i];
                e[4 * i + 0] = sx * w;
                e[4 * i + 1] = sy * w;
                e[4 * i + 2] = cx * w;
                e[4 * i + 3] = cy * w;
                if (i < 7) {
                    float nsx = 2.0f * sx * cx;
                    float ncx = fmaf(-2.0f * sx, sx, 1.0f);
                    float nsy = 2.0f * sy * cy;
                    float ncy = fmaf(-2.0f * sy, sy, 1.0f);
                    sx = nsx; cx = ncx; sy = nsy; cy = ncy;
                }
            }
            uint32_t* ehr = s_eh + (wid * 32 + lane) * 17;
#pragma unroll
            for (int q = 0; q < 16; q++) ehr[q] = packh2(e[2 * q], e[2 * q + 1]);
        }
        __syncwarp();

        // ---- load layer-1 A fragments from smem ----
        uint32_t Ah[2][4][4];
#pragma unroll
        for (int m = 0; m < 2; m++) {
            const int r0 = wid * 32 + m * 16 + g;
            const uint32_t* eh0 = s_eh + r0 * 17;
            const uint32_t* eh1 = eh0 + 8 * 17;
#pragma unroll
            for (int kt = 0; kt < 2; kt++) {
                Ah[m][kt][0] = eh0[kt * 8 + c];
                Ah[m][kt][1] = eh1[kt * 8 + c];
                Ah[m][kt][2] = eh0[kt * 8 + c + 4];
                Ah[m][kt][3] = eh1[kt * 8 + c + 4];
            }
        }
        __syncwarp();

        float C[2][8][4];

        // ---- layer 1 (KT=2) ----
#pragma unroll
        for (int m = 0; m < 2; m++)
#pragma unroll
            for (int n = 0; n < 8; n++)
#pragma unroll
                for (int q = 0; q < 4; q++) C[m][n][q] = 0.0f;
        layer_mma<2>(C, Ah, sm + F1_OFF * 4, lane);
        epilogue(C, (const float*)(sm + SM_ZBASE) + batch * 64, c, Ah);

        // ---- layer 2 (KT=4) ----
#pragma unroll
        for (int m = 0; m < 2; m++)
#pragma unroll
            for (int n = 0; n < 8; n++)
#pragma unroll
                for (int q = 0; q < 4; q++) C[m][n][q] = 0.0f;
        layer_mma<4>(C, Ah, sm + F2_OFF * 4, lane);
        epilogue(C, (const float*)(sm + SM_ZBASE) + 512 + batch * 64, c, Ah);

        // ---- layer 3 (KT=4) ----
#pragma unroll
        for (int m = 0; m < 2; m++)
#pragma unroll
            for (int n = 0; n < 8; n++)
#pragma unroll
                for (int q = 0; q < 4; q++) C[m][n][q] = 0.0f;
        layer_mma<4>(C, Ah, sm + F3_OFF * 4, lane);
        epilogue(C, (const float*)(sm + SM_ZBASE) + 1024 + batch * 64, c, Ah);

        // ---- layer 4: single n8 tile (cols 0..3 real) ----
        float C4[2][4];
#pragma unroll
        for (int m = 0; m < 2; m++)
#pragma unroll
            for (int q = 0; q < 4; q++) C4[m][q] = 0.0f;
#pragma unroll
        for (int kt = 0; kt < 4; kt++) {
            const int off = (kt * 32 + lane) * 8;
            uint2 bh = *(const uint2*)(sm + F4_OFF * 4 + off);
#pragma unroll
            for (int m = 0; m < 2; m++)
                mma16816(C4[m], Ah[m][kt], (const uint32_t*)&bh);
        }

        // ---- masks via shfl (all lanes participate) ----
        float mk[2][2];
#pragma unroll
        for (int m = 0; m < 2; m++) {
            mk[m][0] = __shfl_sync(0xffffffffu, maskv, m * 16 + g);
            mk[m][1] = __shfl_sync(0xffffffffu, maskv, m * 16 + 8 + g);
        }

        // ---- output: threads c<2 hold real cols (2c, 2c+1) ----
        if (c < 2) {
            const float* z4 = (const float*)(sm + SM_ZBASE) + 1536 + batch * 8;
            const float z40 = z4[2 * c], z41 = z4[2 * c + 1];
#pragma unroll
            for (int m = 0; m < 2; m++) {
                const int pix0 = pixbase + m * 16 + g;
                float2 o0, o1;
                o0.x = (C4[m][0] + z40) * mk[m][0];
                o0.y = (C4[m][1] + z41) * mk[m][0];
                o1.x = (C4[m][2] + z40) * mk[m][1];
                o1.y = (C4[m][3] + z41) * mk[m][1];
                *(float2*)(out + pix0 * 4 + 2 * c) = o0;
                *(float2*)(out + (pix0 + 8) * 4 + 2 * c) = o1;
            }
        }
    }
}

// ---------------- launch ----------------
extern "C" void kernel_launch(void* const* d_in, const int* in_sizes, int n_in,
                              void* d_out, int out_size)
{
    const float* coords = (const float*)d_in[0];
    const float* c      = (const float*)d_in[1];
    const float* fu     = (const float*)d_in[2];
    const float* w1     = (const float*)d_in[3];
    const float* b1     = (const float*)d_in[4];
    const float* w2     = (const float*)d_in[5];
    const float* b2     = (const float*)d_in[6];
    const float* w3     = (const float*)d_in[7];
    const float* b3     = (const float*)d_in[8];
    const float* w4     = (const float*)d_in[9];
    const float* b4     = (const float*)d_in[10];
    float* out = (float*)d_out;

    cudaFuncSetAttribute(decoder_kernel, cudaFuncAttributeMaxDynamicSharedMemorySize, SM_TOTAL);
    prep_kernel<<<64, 256>>>(c, fu, w1, b1, w2, b2, w3, b3, w4, b4);
    decoder_kernel<<<GRID_MAIN, TPB, SM_TOTAL>>>(coords, out);
}